// round 12
// baseline (speedup 1.0000x reference)
#include <cuda_runtime.h>
#include <cuda_fp16.h>
#include <cstdint>

#define N_USERS  100000
#define M_ITEMS  50000
#define N_ALL    150000
#define N_EDGES  4800000
#define DIM      64
#define NELEM    (N_ALL * DIM)

// Jacobi coefficients for A=B=1
#define THETA1_K2 1.875f
#define THETA3_K2 0.75f
#define THETA1_K3 (28.0f / 15.0f)

#define SCAN_BLK 1024
#define N_SCAN_BLOCKS ((N_ALL + SCAN_BLK - 1) / SCAN_BLK)   // 147

// Static scratch (allocation-free rule).  128B alignment => every DIM*2=128B
// row of the fp16 shadows occupies exactly ONE L1/L2 cache line.
__device__ __align__(128) float  g_e2f[NELEM];    // fp32 e2 (epilogue operand)
__device__ __align__(128) __half g_hx[3][NELEM];  // fp16 gather shadows: embed,e1,e2
__device__ int   g_count[N_ALL];                  // zero-invariant between calls
__device__ int   g_start[N_ALL + 1];
__device__ int   g_cursor[N_ALL];
__device__ __align__(8) int2 g_epack[N_EDGES];    // (col, val-bits) CSR-ordered
// decoupled-lookback tile state: hi32 = status (0 inval /1 aggregate /2 prefix)
__device__ volatile unsigned long long g_tile[N_SCAN_BLOCKS];

// ---------------------------------------------------------------------------
// hist: row histogram + lookback tile reset  (shadow copy moved to scatter)
// ---------------------------------------------------------------------------
__global__ void hist_kernel(const int* __restrict__ rows) {
    int i = blockIdx.x * blockDim.x + threadIdx.x;
    const int half = N_EDGES / 2;                    // 2,400,000
    if (i < half) {
        atomicAdd(&g_count[__ldg(rows + i)], 1);
        atomicAdd(&g_count[__ldg(rows + i + half)], 1);
    }
    if (i < N_SCAN_BLOCKS) g_tile[i] = 0ull;
}

// ---------------------------------------------------------------------------
// single-pass scan (decoupled lookback)
// ---------------------------------------------------------------------------
__global__ void scan_kernel() {
    __shared__ int sh[SCAN_BLK];
    __shared__ int sh_ex;
    int t   = threadIdx.x;
    int bid = blockIdx.x;
    int i   = bid * SCAN_BLK + t;

    int v = (i < N_ALL) ? g_count[i] : 0;
    if (i < N_ALL) g_count[i] = 0;
    sh[t] = v;
    __syncthreads();
    for (int o = 1; o < SCAN_BLK; o <<= 1) {
        int a = (t >= o) ? sh[t - o] : 0;
        __syncthreads();
        sh[t] += a;
        __syncthreads();
    }
    int total = sh[SCAN_BLK - 1];

    if (t == 0) {
        unsigned long long st = bid == 0
            ? ((2ull << 32) | (unsigned)total)
            : ((1ull << 32) | (unsigned)total);
        g_tile[bid] = st;
    }
    if (t < 32 && bid > 0) {
        int lane = t;
        int base = bid - 1;
        int ex = 0;
        while (true) {
            int idx = base - lane;
            unsigned long long pk;
            int stt, val;
            if (idx >= 0) {
                do { pk = g_tile[idx]; } while ((unsigned)(pk >> 32) == 0u);
                stt = (int)(pk >> 32);
                val = (int)(unsigned)pk;
            } else {
                stt = 2; val = 0;
            }
            unsigned pmask = __ballot_sync(0xFFFFFFFFu, stt == 2);
            int firstp = __ffs(pmask) - 1;
            int contrib = (firstp < 0 || lane <= firstp) ? val : 0;
            #pragma unroll
            for (int o = 16; o > 0; o >>= 1)
                contrib += __shfl_xor_sync(0xFFFFFFFFu, contrib, o);
            ex += contrib;
            if (firstp >= 0) break;
            base -= 32;
        }
        if (lane == 0) {
            g_tile[bid] = (2ull << 32) | (unsigned)(ex + total);
            sh_ex = ex;
        }
    }
    if (t == 0 && bid == 0) sh_ex = 0;
    __syncthreads();

    if (i < N_ALL) {
        int s = sh_ex + sh[t] - v;
        g_start[i]  = s;
        g_cursor[i] = s;
    }
    if (i == 0) g_start[N_ALL] = N_EDGES;
}

// ---------------------------------------------------------------------------
// scatter + fused fp16 shadow copy of embed.  The streaming copy hides the
// scatter's atomic/random-store latency (different pipes, idle otherwise).
// ---------------------------------------------------------------------------
__global__ void scatter_kernel(const int*   __restrict__ rows,
                               const int*   __restrict__ cols,
                               const float* __restrict__ vals,
                               const float* __restrict__ user,
                               const float* __restrict__ item) {
    int e = blockIdx.x * blockDim.x + threadIdx.x;
    if (e >= N_EDGES) return;
    // fused shadow copy: first half of threads convert one float4 each
    const int n4 = NELEM / 4;                        // 2,400,000 = N_EDGES/2
    if (e < n4) {
        float4 v;
        if (e < (N_USERS * DIM) / 4)
            v = ((const float4*)user)[e];
        else
            v = ((const float4*)item)[e - (N_USERS * DIM) / 4];
        __half2 h0 = __floats2half2_rn(v.x, v.y);
        __half2 h1 = __floats2half2_rn(v.z, v.w);
        ((__half2*)g_hx[0])[2 * e]     = h0;
        ((__half2*)g_hx[0])[2 * e + 1] = h1;
    }
    int r = __ldg(rows + e);
    int pos = atomicAdd(&g_cursor[r], 1);
    g_epack[pos] = make_int2(__ldg(cols + e), __float_as_int(__ldg(vals + e)));
}

// ---------------------------------------------------------------------------
// SpMM core: warp per row, 8 lanes per edge (16 B each), lane = g*8+sl.
// R9-proven loop: single accumulator set, 4-edge chunks, unroll 2, fp32 FFMA.
// ---------------------------------------------------------------------------
__device__ __forceinline__ void edge_accum(const __half* __restrict__ hx,
                                           int2 p, int sl, float acc[8]) {
    float v = __int_as_float(p.y);
    uint4 q = __ldg((const uint4*)(hx + (size_t)p.x * DIM) + sl);
    float2 f;
    f = __half22float2(*(__half2*)&q.x); acc[0] += v * f.x; acc[1] += v * f.y;
    f = __half22float2(*(__half2*)&q.y); acc[2] += v * f.x; acc[3] += v * f.y;
    f = __half22float2(*(__half2*)&q.z); acc[4] += v * f.x; acc[5] += v * f.y;
    f = __half22float2(*(__half2*)&q.w); acc[6] += v * f.x; acc[7] += v * f.y;
}

__device__ __forceinline__ void spmm_row(const __half* __restrict__ hx,
                                         int s, int e, int g, int sl,
                                         float acc[8]) {
#pragma unroll
    for (int k = 0; k < 8; k++) acc[k] = 0.f;
    int n  = e - s;
    int n4 = n & ~3;
#pragma unroll 2
    for (int j = s; j < s + n4; j += 4) {
        int2 p = __ldg(&g_epack[j + g]);
        edge_accum(hx, p, sl, acc);
    }
    int rem = n - n4;
    if (g < rem) {
        int2 p = __ldg(&g_epack[s + n4 + g]);
        edge_accum(hx, p, sl, acc);
    }
#pragma unroll
    for (int k = 0; k < 8; k++) {
        acc[k] += __shfl_xor_sync(0xFFFFFFFFu, acc[k], 8);
        acc[k] += __shfl_xor_sync(0xFFFFFFFFu, acc[k], 16);
    }
}

__device__ __forceinline__ uint4 pack_half8(const float a[8]) {
    __half2 h[4];
    h[0] = __floats2half2_rn(a[0], a[1]);
    h[1] = __floats2half2_rn(a[2], a[3]);
    h[2] = __floats2half2_rn(a[4], a[5]);
    h[3] = __floats2half2_rn(a[6], a[7]);
    return *(uint4*)h;
}

__device__ __forceinline__ const float4* embed_row(const float* __restrict__ user,
                                                   const float* __restrict__ item,
                                                   int w) {
    return (w < N_USERS)
        ? (const float4*)(user + (size_t)w * DIM)
        : (const float4*)(item + (size_t)(w - N_USERS) * DIM);
}

// spmm1: e1 = spmm(embed) -> fp16 shadow
__global__ void __launch_bounds__(256) spmm1_kernel() {
    int w = (blockIdx.x * blockDim.x + threadIdx.x) >> 5;
    int lane = threadIdx.x & 31;
    if (w >= N_ALL) return;
    int g = lane >> 3, sl = lane & 7;
    float acc[8];
    spmm_row(g_hx[0], __ldg(&g_start[w]), __ldg(&g_start[w + 1]), g, sl, acc);
    if (g == 0)
        ((uint4*)(g_hx[1] + (size_t)w * DIM))[sl] = pack_half8(acc);
}

// spmm2: e2 = 1.875*spmm(e1) - 0.75*embed -> fp16 shadow + fp32 copy
__global__ void __launch_bounds__(256) spmm2_kernel(const float* __restrict__ user,
                                                    const float* __restrict__ item) {
    int w = (blockIdx.x * blockDim.x + threadIdx.x) >> 5;
    int lane = threadIdx.x & 31;
    if (w >= N_ALL) return;
    int g = lane >> 3, sl = lane & 7;
    float acc[8];
    spmm_row(g_hx[1], __ldg(&g_start[w]), __ldg(&g_start[w + 1]), g, sl, acc);
    if (g < 2) {
        const float4* emp = embed_row(user, item, w);
        float4 em0 = __ldg(emp + 2 * sl), em1 = __ldg(emp + 2 * sl + 1);
        float r[8];
        r[0] = THETA1_K2 * acc[0] - THETA3_K2 * em0.x;
        r[1] = THETA1_K2 * acc[1] - THETA3_K2 * em0.y;
        r[2] = THETA1_K2 * acc[2] - THETA3_K2 * em0.z;
        r[3] = THETA1_K2 * acc[3] - THETA3_K2 * em0.w;
        r[4] = THETA1_K2 * acc[4] - THETA3_K2 * em1.x;
        r[5] = THETA1_K2 * acc[5] - THETA3_K2 * em1.y;
        r[6] = THETA1_K2 * acc[6] - THETA3_K2 * em1.z;
        r[7] = THETA1_K2 * acc[7] - THETA3_K2 * em1.w;
        if (g == 0) {
            ((uint4*)(g_hx[2] + (size_t)w * DIM))[sl] = pack_half8(r);
        } else {
            float4* e2p = (float4*)(g_e2f + (size_t)w * DIM);
            e2p[2 * sl]     = make_float4(r[0], r[1], r[2], r[3]);
            e2p[2 * sl + 1] = make_float4(r[4], r[5], r[6], r[7]);
        }
    }
}

// spmm3 + final epilogue:
//   bs = 0.25*(embed + 0.2*e1 + e2 + (28/15)*acc);  bp = tanh(0.1*embed - bs)
__global__ void __launch_bounds__(256) spmm3_kernel(const float* __restrict__ user,
                                                    const float* __restrict__ item,
                                                    float* __restrict__ out) {
    int w = (blockIdx.x * blockDim.x + threadIdx.x) >> 5;
    int lane = threadIdx.x & 31;
    if (w >= N_ALL) return;
    int g = lane >> 3, sl = lane & 7;
    float acc[8];
    spmm_row(g_hx[2], __ldg(&g_start[w]), __ldg(&g_start[w + 1]), g, sl, acc);
    if (g < 2) {
        const float4* emp = embed_row(user, item, w);
        const float4* a2p = (const float4*)(g_e2f + (size_t)w * DIM);
        float4 em0 = __ldg(emp + 2 * sl), em1 = __ldg(emp + 2 * sl + 1);
        float4 a20 = a2p[2 * sl], a21 = a2p[2 * sl + 1];
        uint4 a1q = ((const uint4*)(g_hx[1] + (size_t)w * DIM))[sl];
        float a1[8];
        {
            float2 f;
            f = __half22float2(*(__half2*)&a1q.x); a1[0] = f.x; a1[1] = f.y;
            f = __half22float2(*(__half2*)&a1q.y); a1[2] = f.x; a1[3] = f.y;
            f = __half22float2(*(__half2*)&a1q.z); a1[4] = f.x; a1[5] = f.y;
            f = __half22float2(*(__half2*)&a1q.w); a1[6] = f.x; a1[7] = f.y;
        }
        float em[8] = {em0.x, em0.y, em0.z, em0.w, em1.x, em1.y, em1.z, em1.w};
        float a2[8] = {a20.x, a20.y, a20.z, a20.w, a21.x, a21.y, a21.z, a21.w};
        float bs[8];
#pragma unroll
        for (int k = 0; k < 8; k++)
            bs[k] = 0.25f * (em[k] + 0.2f * a1[k] + a2[k] + THETA1_K3 * acc[k]);
        float4* orow = (float4*)(out + (size_t)w * 128);
        if (g == 0) {
            orow[2 * sl]     = make_float4(bs[0], bs[1], bs[2], bs[3]);
            orow[2 * sl + 1] = make_float4(bs[4], bs[5], bs[6], bs[7]);
        } else {
            float bp[8];
#pragma unroll
            for (int k = 0; k < 8; k++)
                bp[k] = tanhf(0.1f * em[k] - bs[k]);
            orow[16 + 2 * sl] = make_float4(bp[0], bp[1], bp[2], bp[3]);
            orow[17 + 2 * sl] = make_float4(bp[4], bp[5], bp[6], bp[7]);
        }
    }
}

// ---------------------------------------------------------------------------
extern "C" void kernel_launch(void* const* d_in, const int* in_sizes, int n_in,
                              void* d_out, int out_size) {
    const float* user = (const float*)d_in[0];
    const float* item = (const float*)d_in[1];
    const int*   rows = (const int*)d_in[2];
    const int*   cols = (const int*)d_in[3];
    const float* vals = (const float*)d_in[4];
    float* out = (float*)d_out;

    const int TPB = 256;
    const int hist_blocks = (N_EDGES / 2 + TPB - 1) / TPB;
    const int edge_blocks = (N_EDGES + TPB - 1) / TPB;
    const int spmm_blocks = ((N_ALL * 32) + TPB - 1) / TPB;

    hist_kernel<<<hist_blocks, TPB>>>(rows);
    scan_kernel<<<N_SCAN_BLOCKS, SCAN_BLK>>>();
    scatter_kernel<<<edge_blocks, TPB>>>(rows, cols, vals, user, item);
    spmm1_kernel<<<spmm_blocks, TPB>>>();                  // <- profiled launch
    spmm2_kernel<<<spmm_blocks, TPB>>>(user, item);
    spmm3_kernel<<<spmm_blocks, TPB>>>(user, item, out);
}

// round 13
// speedup vs baseline: 1.0982x; 1.0982x over previous
#include <cuda_runtime.h>
#include <cuda_fp16.h>
#include <cstdint>

#define N_USERS  100000
#define M_ITEMS  50000
#define N_ALL    150000
#define N_EDGES  4800000
#define DIM      64
#define NELEM    (N_ALL * DIM)

// Jacobi coefficients for A=B=1
#define THETA1_K2 1.875f
#define THETA3_K2 0.75f
#define THETA1_K3 (28.0f / 15.0f)

#define SCAN_BLK 1024
#define N_SCAN_BLOCKS ((N_ALL + SCAN_BLK - 1) / SCAN_BLK)   // 147

// Static scratch (allocation-free rule)
__device__ __align__(16) float  g_embed[NELEM];   // fp32 embed
__device__ __align__(16) float  g_e2f[NELEM];     // fp32 e2 (epilogue operand)
__device__ __align__(16) __half g_hx[3][NELEM];   // fp16 gather shadows: embed,e1,e2
__device__ int   g_count[N_ALL];                  // zero-invariant between calls
__device__ int   g_start[N_ALL + 1];
__device__ int   g_cursor[N_ALL];
__device__ __align__(8) int2 g_epack[N_EDGES];    // (col, val-bits) CSR-ordered
__device__ int   g_bsum[N_SCAN_BLOCKS];

// L2-only load for the streamed (zero-reuse) epack entries: keeps L1 free
// for the gathered x rows, which are the only data with reuse value.
__device__ __forceinline__ int2 ldcg_int2(const int2* p) {
    int2 r;
    asm volatile("ld.global.cg.v2.u32 {%0, %1}, [%2];"
                 : "=r"(r.x), "=r"(r.y) : "l"(p));
    return r;
}

// ---------------------------------------------------------------------------
// init: embed = concat(user,item) fp32 + fp16 shadow; fused row histogram
// ---------------------------------------------------------------------------
__global__ void init_kernel(const float* __restrict__ user,
                            const float* __restrict__ item,
                            const int*   __restrict__ rows) {
    int i = blockIdx.x * blockDim.x + threadIdx.x;   // float4 index
    const int n4 = NELEM / 4;                        // 2,400,000
    if (i < n4) {
        float4 v;
        if (i < (N_USERS * DIM) / 4)
            v = ((const float4*)user)[i];
        else
            v = ((const float4*)item)[i - (N_USERS * DIM) / 4];
        ((float4*)g_embed)[i] = v;
        __half2 h0 = __floats2half2_rn(v.x, v.y);
        __half2 h1 = __floats2half2_rn(v.z, v.w);
        ((__half2*)g_hx[0])[2 * i]     = h0;
        ((__half2*)g_hx[0])[2 * i + 1] = h1;
        atomicAdd(&g_count[__ldg(rows + i)], 1);
        atomicAdd(&g_count[__ldg(rows + i + n4)], 1);
    }
}

// ---------------------------------------------------------------------------
// scan stage 1: per-block exclusive scan of counts; re-zero counts
// ---------------------------------------------------------------------------
__global__ void scan1_kernel() {
    __shared__ int sh[SCAN_BLK];
    int t = threadIdx.x;
    int i = blockIdx.x * SCAN_BLK + t;
    int v = (i < N_ALL) ? g_count[i] : 0;
    if (i < N_ALL) g_count[i] = 0;
    sh[t] = v;
    __syncthreads();
    for (int o = 1; o < SCAN_BLK; o <<= 1) {
        int a = (t >= o) ? sh[t - o] : 0;
        __syncthreads();
        sh[t] += a;
        __syncthreads();
    }
    if (i < N_ALL) g_start[i] = sh[t] - v;
    if (t == SCAN_BLK - 1) g_bsum[blockIdx.x] = sh[t];
}

// scan stage 2: parallel exclusive scan of 147 block sums
__global__ void scan2_kernel() {
    __shared__ int sh[256];
    int t = threadIdx.x;
    int v = (t < N_SCAN_BLOCKS) ? g_bsum[t] : 0;
    sh[t] = v;
    __syncthreads();
    for (int o = 1; o < 256; o <<= 1) {
        int a = (t >= o) ? sh[t - o] : 0;
        __syncthreads();
        sh[t] += a;
        __syncthreads();
    }
    if (t < N_SCAN_BLOCKS) g_bsum[t] = sh[t] - v;
}

// scan stage 3: add block offsets; init cursors; sentinel
__global__ void scan3_kernel() {
    int i = blockIdx.x * SCAN_BLK + threadIdx.x;
    if (i < N_ALL) {
        int s = g_start[i] + g_bsum[blockIdx.x];
        g_start[i]  = s;
        g_cursor[i] = s;
    }
    if (i == 0) g_start[N_ALL] = N_EDGES;
}

// ---------------------------------------------------------------------------
// scatter edges into CSR order
// ---------------------------------------------------------------------------
__global__ void scatter_kernel(const int*   __restrict__ rows,
                               const int*   __restrict__ cols,
                               const float* __restrict__ vals) {
    int e = blockIdx.x * blockDim.x + threadIdx.x;
    if (e >= N_EDGES) return;
    int r = __ldg(rows + e);
    int pos = atomicAdd(&g_cursor[r], 1);
    g_epack[pos] = make_int2(__ldg(cols + e), __float_as_int(__ldg(vals + e)));
}

// ---------------------------------------------------------------------------
// SpMM core: warp per row, 8 lanes per edge (16 B each), lane = g*8+sl.
// R4-proven loop: single accumulator set, 4-edge chunks, unroll 2.
// epack loads go L2-only (ldcg) to avoid polluting L1.
// ---------------------------------------------------------------------------
__device__ __forceinline__ void edge_accum(const __half* __restrict__ hx,
                                           int2 p, int sl, float acc[8]) {
    float v = __int_as_float(p.y);
    uint4 q = __ldg((const uint4*)(hx + (size_t)p.x * DIM) + sl);
    float2 f;
    f = __half22float2(*(__half2*)&q.x); acc[0] += v * f.x; acc[1] += v * f.y;
    f = __half22float2(*(__half2*)&q.y); acc[2] += v * f.x; acc[3] += v * f.y;
    f = __half22float2(*(__half2*)&q.z); acc[4] += v * f.x; acc[5] += v * f.y;
    f = __half22float2(*(__half2*)&q.w); acc[6] += v * f.x; acc[7] += v * f.y;
}

__device__ __forceinline__ void spmm_row(const __half* __restrict__ hx,
                                         int s, int e, int g, int sl,
                                         float acc[8]) {
#pragma unroll
    for (int k = 0; k < 8; k++) acc[k] = 0.f;
    int n  = e - s;
    int n4 = n & ~3;
#pragma unroll 2
    for (int j = s; j < s + n4; j += 4) {
        int2 p = ldcg_int2(&g_epack[j + g]);
        edge_accum(hx, p, sl, acc);
    }
    int rem = n - n4;
    if (g < rem) {
        int2 p = ldcg_int2(&g_epack[s + n4 + g]);
        edge_accum(hx, p, sl, acc);
    }
#pragma unroll
    for (int k = 0; k < 8; k++) {
        acc[k] += __shfl_xor_sync(0xFFFFFFFFu, acc[k], 8);
        acc[k] += __shfl_xor_sync(0xFFFFFFFFu, acc[k], 16);
    }
}

__device__ __forceinline__ uint4 pack_half8(const float a[8]) {
    __half2 h[4];
    h[0] = __floats2half2_rn(a[0], a[1]);
    h[1] = __floats2half2_rn(a[2], a[3]);
    h[2] = __floats2half2_rn(a[4], a[5]);
    h[3] = __floats2half2_rn(a[6], a[7]);
    return *(uint4*)h;
}

// spmm1: e1 = spmm(embed) -> fp16 shadow
__global__ void __launch_bounds__(256) spmm1_kernel() {
    int w = (blockIdx.x * blockDim.x + threadIdx.x) >> 5;
    int lane = threadIdx.x & 31;
    if (w >= N_ALL) return;
    int g = lane >> 3, sl = lane & 7;
    float acc[8];
    spmm_row(g_hx[0], g_start[w], g_start[w + 1], g, sl, acc);
    if (g == 0)
        ((uint4*)(g_hx[1] + (size_t)w * DIM))[sl] = pack_half8(acc);
}

// spmm2: e2 = 1.875*spmm(e1) - 0.75*embed -> fp16 shadow + fp32 copy
__global__ void __launch_bounds__(256) spmm2_kernel() {
    int w = (blockIdx.x * blockDim.x + threadIdx.x) >> 5;
    int lane = threadIdx.x & 31;
    if (w >= N_ALL) return;
    int g = lane >> 3, sl = lane & 7;
    float acc[8];
    spmm_row(g_hx[1], g_start[w], g_start[w + 1], g, sl, acc);
    if (g < 2) {
        const float4* emp = (const float4*)(g_embed + (size_t)w * DIM);
        float4 em0 = emp[2 * sl], em1 = emp[2 * sl + 1];
        float r[8];
        r[0] = THETA1_K2 * acc[0] - THETA3_K2 * em0.x;
        r[1] = THETA1_K2 * acc[1] - THETA3_K2 * em0.y;
        r[2] = THETA1_K2 * acc[2] - THETA3_K2 * em0.z;
        r[3] = THETA1_K2 * acc[3] - THETA3_K2 * em0.w;
        r[4] = THETA1_K2 * acc[4] - THETA3_K2 * em1.x;
        r[5] = THETA1_K2 * acc[5] - THETA3_K2 * em1.y;
        r[6] = THETA1_K2 * acc[6] - THETA3_K2 * em1.z;
        r[7] = THETA1_K2 * acc[7] - THETA3_K2 * em1.w;
        if (g == 0) {
            ((uint4*)(g_hx[2] + (size_t)w * DIM))[sl] = pack_half8(r);
        } else {
            float4* e2p = (float4*)(g_e2f + (size_t)w * DIM);
            e2p[2 * sl]     = make_float4(r[0], r[1], r[2], r[3]);
            e2p[2 * sl + 1] = make_float4(r[4], r[5], r[6], r[7]);
        }
    }
}

// spmm3 + final epilogue:
//   bs = 0.25*(embed + 0.2*e1 + e2 + (28/15)*acc);  bp = tanh(0.1*embed - bs)
__global__ void __launch_bounds__(256) spmm3_kernel(float* __restrict__ out) {
    int w = (blockIdx.x * blockDim.x + threadIdx.x) >> 5;
    int lane = threadIdx.x & 31;
    if (w >= N_ALL) return;
    int g = lane >> 3, sl = lane & 7;
    float acc[8];
    spmm_row(g_hx[2], g_start[w], g_start[w + 1], g, sl, acc);
    if (g < 2) {
        const float4* emp = (const float4*)(g_embed + (size_t)w * DIM);
        const float4* a2p = (const float4*)(g_e2f  + (size_t)w * DIM);
        float4 em0 = emp[2 * sl], em1 = emp[2 * sl + 1];
        float4 a20 = a2p[2 * sl], a21 = a2p[2 * sl + 1];
        uint4 a1q = ((const uint4*)(g_hx[1] + (size_t)w * DIM))[sl];
        float a1[8];
        {
            float2 f;
            f = __half22float2(*(__half2*)&a1q.x); a1[0] = f.x; a1[1] = f.y;
            f = __half22float2(*(__half2*)&a1q.y); a1[2] = f.x; a1[3] = f.y;
            f = __half22float2(*(__half2*)&a1q.z); a1[4] = f.x; a1[5] = f.y;
            f = __half22float2(*(__half2*)&a1q.w); a1[6] = f.x; a1[7] = f.y;
        }
        float em[8] = {em0.x, em0.y, em0.z, em0.w, em1.x, em1.y, em1.z, em1.w};
        float a2[8] = {a20.x, a20.y, a20.z, a20.w, a21.x, a21.y, a21.z, a21.w};
        float bs[8];
#pragma unroll
        for (int k = 0; k < 8; k++)
            bs[k] = 0.25f * (em[k] + 0.2f * a1[k] + a2[k] + THETA1_K3 * acc[k]);
        float4* orow = (float4*)(out + (size_t)w * 128);
        if (g == 0) {
            orow[2 * sl]     = make_float4(bs[0], bs[1], bs[2], bs[3]);
            orow[2 * sl + 1] = make_float4(bs[4], bs[5], bs[6], bs[7]);
        } else {
            float bp[8];
#pragma unroll
            for (int k = 0; k < 8; k++)
                bp[k] = tanhf(0.1f * em[k] - bs[k]);
            orow[16 + 2 * sl] = make_float4(bp[0], bp[1], bp[2], bp[3]);
            orow[17 + 2 * sl] = make_float4(bp[4], bp[5], bp[6], bp[7]);
        }
    }
}

// ---------------------------------------------------------------------------
extern "C" void kernel_launch(void* const* d_in, const int* in_sizes, int n_in,
                              void* d_out, int out_size) {
    const float* user = (const float*)d_in[0];
    const float* item = (const float*)d_in[1];
    const int*   rows = (const int*)d_in[2];
    const int*   cols = (const int*)d_in[3];
    const float* vals = (const float*)d_in[4];
    float* out = (float*)d_out;

    const int TPB = 256;
    const int init_blocks = (NELEM / 4 + TPB - 1) / TPB;
    const int edge_blocks = (N_EDGES + TPB - 1) / TPB;
    const int spmm_blocks = ((N_ALL * 32) + TPB - 1) / TPB;

    init_kernel<<<init_blocks, TPB>>>(user, item, rows);
    scan1_kernel<<<N_SCAN_BLOCKS, SCAN_BLK>>>();
    scan2_kernel<<<1, 256>>>();
    scan3_kernel<<<N_SCAN_BLOCKS, SCAN_BLK>>>();
    scatter_kernel<<<edge_blocks, TPB>>>(rows, cols, vals);
    spmm1_kernel<<<spmm_blocks, TPB>>>();
    spmm2_kernel<<<spmm_blocks, TPB>>>();
    spmm3_kernel<<<spmm_blocks, TPB>>>(out);
}